// round 1
// baseline (speedup 1.0000x reference)
#include <cuda_runtime.h>
#include <math.h>

#define D 64
#define NNODES 512
#define NTOT 4096
#define HDIM 192
#define TILE_E 64
#define EMAX 131072
#define SMEM_BYTES ((HDIM*HDIM + TILE_E*HDIM + HDIM) * sizeof(float))

__device__ float g_scores[EMAX];
__device__ float g_denom[NTOT];
__device__ int   g_is64;

__device__ __forceinline__ long long ldidx(const void* ei, int i, int is64) {
    return is64 ? ((const long long*)ei)[i] : (long long)((const int*)ei)[i];
}

// Detect whether edge_index arrived as int64 or int32 (JAX x64-default ambiguity).
// Interpreting int32 data as int64 packs two entries per value; high word is a
// src/dst index (nonzero with prob ~511/512 per entry), so out-of-range values
// appear almost surely within 1024 probes.
__global__ void detect_kernel(const void* __restrict__ ei) {
    const long long* p = (const long long*)ei;
    int ok = 1;
    for (int i = 0; i < 1024; ++i) {
        long long v = p[i];
        if (v < 0 || v >= NTOT) { ok = 0; break; }
    }
    g_is64 = ok;
}

__global__ void zero_kernel(float* __restrict__ out) {
    int i = blockIdx.x * blockDim.x + threadIdx.x;
    if (i < NTOT * D) out[i] = 0.0f;
    if (i < NTOT)     g_denom[i] = 0.0f;
}

// Persistent blocks: W1^T staged in smem once per block, then loop over
// 64-edge tiles. Per tile: gather H [64 x 192] to smem, register-blocked
// matvec (8 edges x 6 outputs per thread), fused GELU * W2 + warp reduce,
// masked exp score -> scratch + atomic denom.
__global__ __launch_bounds__(256, 1) void score_kernel(
    const float* __restrict__ nf, const float* __restrict__ adj,
    const float* __restrict__ W1, const float* __restrict__ W2,
    const void* __restrict__ ei, int E, int ntiles)
{
    extern __shared__ float sm[];
    float* Ws  = sm;                       // [192][192], Ws[k*192+o] = W1[o][k]
    float* Hs  = sm + HDIM * HDIM;         // [64][192]
    float* W2s = Hs + TILE_E * HDIM;       // [192]

    int tid  = threadIdx.x;
    int lane = tid & 31;
    int warp = tid >> 5;
    int is64 = g_is64;

    for (int i = tid; i < HDIM * HDIM; i += 256) {
        int o = i / HDIM, k = i - o * HDIM;
        Ws[k * HDIM + o] = W1[i];          // coalesced read, transpose to smem
    }
    for (int i = tid; i < HDIM; i += 256) W2s[i] = W2[i];

    for (int tile = blockIdx.x; tile < ntiles; tile += gridDim.x) {
        int e0 = tile * TILE_E;
        __syncthreads();  // protect Hs from previous iteration's readers

        // Gather H tile: per edge 48 float4 = [nf[dst](16) | nf[src](16) | adj row(16)]
        for (int i = tid; i < TILE_E * 48; i += 256) {
            int e = i / 48, r = i - e * 48;
            int ge = e0 + e;
            float4 v = make_float4(0.f, 0.f, 0.f, 0.f);
            if (ge < E) {
                long long s = ldidx(ei, ge, is64);
                long long d = ldidx(ei, E + ge, is64);
                const float4* p;
                if (r < 16)      p = (const float4*)(nf + d * D) + r;
                else if (r < 32) p = (const float4*)(nf + s * D) + (r - 16);
                else             p = (const float4*)(adj + (s * (long long)NNODES + (int)(d % NNODES)) * D) + (r - 32);
                v = *p;
            }
            ((float4*)(Hs + e * HDIM))[r] = v;
        }
        __syncthreads();

        float acc[8][6];
        #pragma unroll
        for (int e = 0; e < 8; ++e)
            #pragma unroll
            for (int j = 0; j < 6; ++j) acc[e][j] = 0.0f;

        const float* hb = Hs + (warp * 8) * HDIM;
        #pragma unroll 2
        for (int k = 0; k < HDIM; ++k) {
            const float* w = Ws + k * HDIM + lane;   // bank = lane: conflict-free
            float wv[6];
            #pragma unroll
            for (int j = 0; j < 6; ++j) wv[j] = w[32 * j];
            #pragma unroll
            for (int e = 0; e < 8; ++e) {
                float hv = hb[e * HDIM + k];         // warp broadcast
                #pragma unroll
                for (int j = 0; j < 6; ++j) acc[e][j] = fmaf(hv, wv[j], acc[e][j]);
            }
        }

        // Epilogue: z = sum_o gelu(y_o) * W2[o]; exp; mask; denom atomic
        #pragma unroll
        for (int e = 0; e < 8; ++e) {
            float p = 0.0f;
            #pragma unroll
            for (int j = 0; j < 6; ++j) {
                float x = acc[e][j];
                float g = 0.5f * x * (1.0f + erff(x * 0.70710678118654752f));
                p += g * W2s[lane + 32 * j];
            }
            #pragma unroll
            for (int off = 16; off; off >>= 1) p += __shfl_xor_sync(0xffffffffu, p, off);
            if (lane == 0) {
                int ge = e0 + warp * 8 + e;
                if (ge < E) {
                    long long s = ldidx(ei, ge, is64);
                    long long d = ldidx(ei, E + ge, is64);
                    long long diff = s > d ? s - d : d - s;
                    float attn = 0.0f;
                    if (diff > 1) attn = expf(p);
                    g_scores[ge] = attn;
                    if (attn != 0.0f) atomicAdd(&g_denom[(int)d], attn);
                }
            }
        }
    }
}

// One warp per edge: re-gather the adj row (L2-resident from pass 1),
// normalize, accumulate into out with fp32 atomics (2 cols / lane).
__global__ __launch_bounds__(256) void aggregate_kernel(
    const float* __restrict__ adj, const void* __restrict__ ei,
    float* __restrict__ out, int E)
{
    int gw   = (blockIdx.x * blockDim.x + threadIdx.x) >> 5;
    int lane = threadIdx.x & 31;
    if (gw >= E) return;
    float s = g_scores[gw];
    if (s == 0.0f) return;
    int is64 = g_is64;
    long long src = ldidx(ei, gw, is64);
    long long dst = ldidx(ei, E + gw, is64);
    float dn = g_denom[(int)dst];
    float attn = s / (dn == 0.0f ? 1.0f : dn);
    const float2* er = (const float2*)(adj + (src * (long long)NNODES + (int)(dst % NNODES)) * D);
    float2 v = er[lane];
    float* o = out + (int)dst * D + 2 * lane;
    atomicAdd(o,     v.x * attn);
    atomicAdd(o + 1, v.y * attn);
}

extern "C" void kernel_launch(void* const* d_in, const int* in_sizes, int n_in,
                              void* d_out, int out_size) {
    const float* nf  = (const float*)d_in[0];
    const float* adj = (const float*)d_in[1];
    const float* W1  = (const float*)d_in[2];
    const float* W2  = (const float*)d_in[3];
    const void*  ei  = d_in[4];
    int E = in_sizes[4] / 2;
    if (E > EMAX) E = EMAX;

    cudaFuncSetAttribute(score_kernel, cudaFuncAttributeMaxDynamicSharedMemorySize,
                         (int)SMEM_BYTES);

    detect_kernel<<<1, 1>>>(ei);
    zero_kernel<<<(NTOT * D + 255) / 256, 256>>>((float*)d_out);

    int ntiles = (E + TILE_E - 1) / TILE_E;
    int grid = ntiles < 148 ? ntiles : 148;
    score_kernel<<<grid, 256, SMEM_BYTES>>>(nf, adj, W1, W2, ei, E, ntiles);

    int aggblocks = (E * 32 + 255) / 256;
    aggregate_kernel<<<aggblocks, 256>>>(adj, ei, (float*)d_out, E);
}

// round 2
// speedup vs baseline: 2.4153x; 2.4153x over previous
#include <cuda_runtime.h>
#include <math.h>

#define D 64
#define NNODES 512
#define NTOT 4096
#define HDIM 192
#define TILE_E 64
#define EMAX 131072

// Scratch (no allocations allowed in kernel_launch)
__device__ float g_denom[NTOT];
__device__ float g_Pd[NTOT * HDIM];   // nf @ W1[:,0:64]^T   (dst contribution)
__device__ float g_Ps[NTOT * HDIM];   // nf @ W1[:,64:128]^T (src contribution)
__device__ int   g_is64;

__device__ __forceinline__ long long ldidx(const void* ei, int i, int is64) {
    return is64 ? ((const long long*)ei)[i] : (long long)((const int*)ei)[i];
}

// Detect int64 vs int32 edge_index (probe high words via range check).
__global__ void detect_kernel(const void* __restrict__ ei) {
    const long long* p = (const long long*)ei;
    int ok = 1;
    for (int i = 0; i < 1024; ++i) {
        long long v = p[i];
        if (v < 0 || v >= NTOT) { ok = 0; break; }
    }
    g_is64 = ok;
}

__global__ void zero_kernel(float* __restrict__ out) {
    int i = blockIdx.x * blockDim.x + threadIdx.x;
    if (i < NTOT * D) out[i] = 0.0f;
    if (i < NTOT)     g_denom[i] = 0.0f;
}

// P[n][o] = sum_k nf[n][k] * W1[o][64*half + k]   (half 0 -> Pd, half 1 -> Ps)
// One block = 64 nodes x one half. 128 blocks total.
__global__ __launch_bounds__(256, 2) void precompute_kernel(
    const float* __restrict__ nf, const float* __restrict__ W1)
{
    extern __shared__ float sm[];
    float* Ws = sm;                 // [64][192] transposed: Ws[k*192+o] = W1[o][64*half+k]
    float* Ns = sm + 64 * HDIM;     // [64][64] node tile

    int half = blockIdx.x & 1;
    int tile = blockIdx.x >> 1;
    int tid  = threadIdx.x;
    int lane = tid & 31;
    int warp = tid >> 5;
    float* P = half ? g_Ps : g_Pd;

    for (int i = tid; i < HDIM * 64; i += 256) {
        int o = i >> 6, k = i & 63;
        Ws[k * HDIM + o] = W1[o * HDIM + 64 * half + k];
    }
    for (int i = tid; i < 64 * 64 / 4; i += 256) {
        ((float4*)Ns)[i] = ((const float4*)(nf + tile * 64 * D))[i];
    }
    __syncthreads();

    float acc[8][6];
    #pragma unroll
    for (int e = 0; e < 8; ++e)
        #pragma unroll
        for (int j = 0; j < 6; ++j) acc[e][j] = 0.0f;

    const float* hb = Ns + (warp * 8) * 64;
    #pragma unroll 4
    for (int k = 0; k < 64; ++k) {
        const float* w = Ws + k * HDIM + lane;
        float wv[6];
        #pragma unroll
        for (int j = 0; j < 6; ++j) wv[j] = w[32 * j];
        #pragma unroll
        for (int e = 0; e < 8; ++e) {
            float hv = hb[e * 64 + k];
            #pragma unroll
            for (int j = 0; j < 6; ++j) acc[e][j] = fmaf(hv, wv[j], acc[e][j]);
        }
    }

    int nbase = tile * 64 + warp * 8;
    #pragma unroll
    for (int e = 0; e < 8; ++e)
        #pragma unroll
        for (int j = 0; j < 6; ++j)
            P[(nbase + e) * HDIM + lane + 32 * j] = acc[e][j];
}

// Fused score + weighted accumulate.
// Per 64-edge tile: gather adj rows [64x64] to smem, K=64 matvec vs W1c^T,
// add Pd[dst]+Ps[src], exact GELU, dot W2, exp, mask; then atomically add
// attn into denom[dst] and attn*edge_row into out[dst] (normalize later).
__global__ __launch_bounds__(256, 2) void score_kernel(
    const float* __restrict__ adj, const float* __restrict__ W1,
    const float* __restrict__ W2, const void* __restrict__ ei,
    float* __restrict__ out, int E, int ntiles)
{
    extern __shared__ float sm[];
    float* Ws  = sm;                    // [64][192]: Ws[k*192+o] = W1[o][128+k]
    float* Hs  = sm + 64 * HDIM;        // [64][64] edge rows
    float* W2s = Hs + TILE_E * 64;      // [192]
    int*   sS  = (int*)(W2s + HDIM);    // [64] src
    int*   sD  = sS + TILE_E;           // [64] dst

    int tid  = threadIdx.x;
    int lane = tid & 31;
    int warp = tid >> 5;
    int is64 = g_is64;

    for (int i = tid; i < HDIM * 64; i += 256) {
        int o = i >> 6, k = i & 63;
        Ws[k * HDIM + o] = W1[o * HDIM + 128 + k];
    }
    for (int i = tid; i < HDIM; i += 256) W2s[i] = W2[i];

    for (int tile = blockIdx.x; tile < ntiles; tile += gridDim.x) {
        int e0 = tile * TILE_E;
        __syncthreads();   // protect Hs/sS/sD from previous iteration readers

        // Gather: per edge 16 float4 of the adj row; also stash indices.
        for (int i = tid; i < TILE_E * 16; i += 256) {
            int e = i >> 4, r = i & 15;
            int ge = e0 + e;
            float4 v = make_float4(0.f, 0.f, 0.f, 0.f);
            if (ge < E) {
                long long s = ldidx(ei, ge, is64);
                long long d = ldidx(ei, E + ge, is64);
                if (r == 0) { sS[e] = (int)s; sD[e] = (int)d; }
                v = ((const float4*)(adj + (s * (long long)NNODES + (int)(d % NNODES)) * D))[r];
            } else if (r == 0) { sS[e] = 0; sD[e] = 0; }
            ((float4*)(Hs + e * 64))[r] = v;
        }
        __syncthreads();

        float acc[8][6];
        #pragma unroll
        for (int e = 0; e < 8; ++e)
            #pragma unroll
            for (int j = 0; j < 6; ++j) acc[e][j] = 0.0f;

        const float* hb = Hs + (warp * 8) * 64;
        #pragma unroll 4
        for (int k = 0; k < 64; ++k) {
            const float* w = Ws + k * HDIM + lane;
            float wv[6];
            #pragma unroll
            for (int j = 0; j < 6; ++j) wv[j] = w[32 * j];
            #pragma unroll
            for (int e = 0; e < 8; ++e) {
                float hv = hb[e * 64 + k];
                #pragma unroll
                for (int j = 0; j < 6; ++j) acc[e][j] = fmaf(hv, wv[j], acc[e][j]);
            }
        }

        #pragma unroll
        for (int e = 0; e < 8; ++e) {
            int eidx = warp * 8 + e;
            int ge = e0 + eidx;
            int s = sS[eidx], d = sD[eidx];
            const float* pd = g_Pd + d * HDIM;
            const float* ps = g_Ps + s * HDIM;
            float p = 0.0f;
            #pragma unroll
            for (int j = 0; j < 6; ++j) {
                int o = lane + 32 * j;
                float x = acc[e][j] + pd[o] + ps[o];
                float g = 0.5f * x * (1.0f + erff(x * 0.70710678118654752f));
                p = fmaf(g, W2s[o], p);
            }
            #pragma unroll
            for (int off = 16; off; off >>= 1) p += __shfl_xor_sync(0xffffffffu, p, off);

            int diff = s > d ? s - d : d - s;
            float attn = (diff > 1 && ge < E) ? expf(p) : 0.0f;
            if (attn != 0.0f) {
                if (lane == 0) atomicAdd(&g_denom[d], attn);
                float2 v = ((const float2*)(Hs + eidx * 64))[lane];
                float* o = out + d * D + 2 * lane;
                atomicAdd(o,     v.x * attn);
                atomicAdd(o + 1, v.y * attn);
            }
        }
    }
}

__global__ void finalize_kernel(float* __restrict__ out) {
    int i = blockIdx.x * blockDim.x + threadIdx.x;
    if (i < NTOT * D) {
        float dn = g_denom[i >> 6];
        out[i] = out[i] / (dn == 0.0f ? 1.0f : dn);
    }
}

extern "C" void kernel_launch(void* const* d_in, const int* in_sizes, int n_in,
                              void* d_out, int out_size) {
    const float* nf  = (const float*)d_in[0];
    const float* adj = (const float*)d_in[1];
    const float* W1  = (const float*)d_in[2];
    const float* W2  = (const float*)d_in[3];
    const void*  ei  = d_in[4];
    int E = in_sizes[4] / 2;
    if (E > EMAX) E = EMAX;

    const int pre_smem   = (64 * HDIM + 64 * 64) * sizeof(float);
    const int score_smem = (64 * HDIM + TILE_E * 64 + HDIM) * sizeof(float)
                         + 2 * TILE_E * sizeof(int);
    cudaFuncSetAttribute(precompute_kernel, cudaFuncAttributeMaxDynamicSharedMemorySize, pre_smem);
    cudaFuncSetAttribute(score_kernel,      cudaFuncAttributeMaxDynamicSharedMemorySize, score_smem);

    detect_kernel<<<1, 1>>>(ei);
    zero_kernel<<<(NTOT * D + 255) / 256, 256>>>((float*)d_out);
    precompute_kernel<<<(NTOT / 64) * 2, 256, pre_smem>>>(nf, W1);

    int ntiles = (E + TILE_E - 1) / TILE_E;
    int grid = ntiles < 296 ? ntiles : 296;
    score_kernel<<<grid, 256, score_smem>>>(adj, W1, W2, ei, (float*)d_out, E, ntiles);

    finalize_kernel<<<(NTOT * D + 255) / 256, 256>>>((float*)d_out);
}

// round 4
// speedup vs baseline: 3.8839x; 1.6081x over previous
#include <cuda_runtime.h>
#include <cuda_bf16.h>
#include <math.h>
#include <stdint.h>

#define D 64
#define NNODES 512
#define NTOT 4096
#define HDIM 192
#define EMAX 131072
#define NWARP 16
#define THREADS (NWARP * 32)

// ---- smem layout (bytes). Rows padded to 144B (9x16B) => conflict-free ldmatrix ----
#define ROWB 144
#define OFF_WHI 0                         // [192][72] bf16  -> 27648
#define OFF_WLO 27648                     // 27648
#define OFF_W2  55296                     // 192 f32 -> 768
#define OFF_A   56064                     // 16 warps x (hi 2304 + lo 2304) = 73728
#define AWARP   4608
#define OFF_SS  129792                    // 16w x 16 int
#define OFF_SD  130816
#define OFF_AT  131840
#define SMEM_TOTAL 132864

__device__ float g_denom[NTOT];
__device__ float g_Pd[NTOT * HDIM];
__device__ float g_Ps[NTOT * HDIM];
__device__ int   g_is64;

__device__ __forceinline__ long long ldidx(const void* ei, int i, int is64) {
    return is64 ? ((const long long*)ei)[i] : (long long)((const int*)ei)[i];
}

__device__ __forceinline__ void ldsm4(uint32_t* r, uint32_t a) {
    asm volatile("ldmatrix.sync.aligned.m8n8.x4.shared.b16 {%0,%1,%2,%3}, [%4];"
                 : "=r"(r[0]), "=r"(r[1]), "=r"(r[2]), "=r"(r[3]) : "r"(a));
}
__device__ __forceinline__ void ldsm2(uint32_t* r, uint32_t a) {
    asm volatile("ldmatrix.sync.aligned.m8n8.x2.shared.b16 {%0,%1}, [%2];"
                 : "=r"(r[0]), "=r"(r[1]) : "r"(a));
}
__device__ __forceinline__ void mma_bf16(float* c, const uint32_t* a, const uint32_t* b) {
    asm volatile("mma.sync.aligned.m16n8k16.row.col.f32.bf16.bf16.f32 "
                 "{%0,%1,%2,%3}, {%4,%5,%6,%7}, {%8,%9}, {%0,%1,%2,%3};"
                 : "+f"(c[0]), "+f"(c[1]), "+f"(c[2]), "+f"(c[3])
                 : "r"(a[0]), "r"(a[1]), "r"(a[2]), "r"(a[3]), "r"(b[0]), "r"(b[1]));
}
__device__ __forceinline__ void red4(float* p, float a, float b, float c, float d) {
    asm volatile("red.global.add.v4.f32 [%0], {%1,%2,%3,%4};"
                 :: "l"(p), "f"(a), "f"(b), "f"(c), "f"(d) : "memory");
}
__device__ __forceinline__ uint2 pack_hi_lo(float4 v, uint2* lo) {
    __nv_bfloat16 h0 = __float2bfloat16(v.x), h1 = __float2bfloat16(v.y);
    __nv_bfloat16 h2 = __float2bfloat16(v.z), h3 = __float2bfloat16(v.w);
    __nv_bfloat16 l0 = __float2bfloat16(v.x - __bfloat162float(h0));
    __nv_bfloat16 l1 = __float2bfloat16(v.y - __bfloat162float(h1));
    __nv_bfloat16 l2 = __float2bfloat16(v.z - __bfloat162float(h2));
    __nv_bfloat16 l3 = __float2bfloat16(v.w - __bfloat162float(h3));
    uint2 hi, lv;
    hi.x = (uint32_t)__bfloat16_as_ushort(h0) | ((uint32_t)__bfloat16_as_ushort(h1) << 16);
    hi.y = (uint32_t)__bfloat16_as_ushort(h2) | ((uint32_t)__bfloat16_as_ushort(h3) << 16);
    lv.x = (uint32_t)__bfloat16_as_ushort(l0) | ((uint32_t)__bfloat16_as_ushort(l1) << 16);
    lv.y = (uint32_t)__bfloat16_as_ushort(l2) | ((uint32_t)__bfloat16_as_ushort(l3) << 16);
    *lo = lv;
    return hi;
}
__device__ __forceinline__ float2 ubf2(uint32_t u) {
    __nv_bfloat162 b = *reinterpret_cast<__nv_bfloat162*>(&u);
    return __bfloat1622float2(b);
}
__device__ __forceinline__ float gelu_x(float x) {
    return 0.5f * x * (1.0f + erff(x * 0.70710678118654752f));
}

__global__ void detect_kernel(const void* __restrict__ ei) {
    const long long* p = (const long long*)ei;
    long long v = p[threadIdx.x];
    int ok = (v >= 0 && v < NTOT);
    int all = __syncthreads_and(ok);
    if (threadIdx.x == 0) g_is64 = all;
}

__global__ void zero_kernel(float* __restrict__ out) {
    int i = blockIdx.x * blockDim.x + threadIdx.x;
    if (i < NTOT * D) out[i] = 0.0f;
    if (i < NTOT)     g_denom[i] = 0.0f;
}

// Pd/Ps: P[n][o] = sum_k nf[n][k] * W1[o][64*half + k]  (fp32 exact)
__global__ __launch_bounds__(256, 2) void precompute_kernel(
    const float* __restrict__ nf, const float* __restrict__ W1)
{
    extern __shared__ float psm[];
    float* Ws = psm;                // [64][192]: Ws[k*192+o]
    float* Ns = psm + 64 * HDIM;    // [64][64]

    int half = blockIdx.x & 1;
    int tile = blockIdx.x >> 1;
    int tid = threadIdx.x, lane = tid & 31, warp = tid >> 5;
    float* P = half ? g_Ps : g_Pd;

    for (int i = tid; i < HDIM * 64; i += 256) {
        int o = i >> 6, k = i & 63;
        Ws[k * HDIM + o] = W1[o * HDIM + 64 * half + k];
    }
    for (int i = tid; i < 64 * 64 / 4; i += 256)
        ((float4*)Ns)[i] = ((const float4*)(nf + tile * 64 * D))[i];
    __syncthreads();

    float acc[8][6];
    #pragma unroll
    for (int e = 0; e < 8; ++e)
        #pragma unroll
        for (int j = 0; j < 6; ++j) acc[e][j] = 0.0f;

    const float* hb = Ns + (warp * 8) * 64;
    #pragma unroll 4
    for (int k = 0; k < 64; ++k) {
        const float* w = Ws + k * HDIM + lane;
        float wv[6];
        #pragma unroll
        for (int j = 0; j < 6; ++j) wv[j] = w[32 * j];
        #pragma unroll
        for (int e = 0; e < 8; ++e) {
            float hv = hb[e * 64 + k];
            #pragma unroll
            for (int j = 0; j < 6; ++j) acc[e][j] = fmaf(hv, wv[j], acc[e][j]);
        }
    }
    int nbase = tile * 64 + warp * 8;
    #pragma unroll
    for (int e = 0; e < 8; ++e)
        #pragma unroll
        for (int j = 0; j < 6; ++j)
            P[(nbase + e) * HDIM + lane + 32 * j] = acc[e][j];
}

// Warp-autonomous fused kernel: per 16-edge warp-tile, bf16-split HMMA GEMM
// (K=64 adj part), acc initialized with Pd[dst]+Ps[src], gelu*W2 epilogue,
// exp/mask, denom atomic, red.v4 weighted accumulate.
__global__ __launch_bounds__(THREADS, 1) void score_kernel(
    const float* __restrict__ adj, const float* __restrict__ W1,
    const float* __restrict__ W2, const void* __restrict__ ei,
    float* __restrict__ out, int E, int nwt)
{
    extern __shared__ __align__(16) char sm[];
    uint32_t smb = (uint32_t)__cvta_generic_to_shared(sm);
    float* W2s = (float*)(sm + OFF_W2);

    int tid = threadIdx.x, lane = tid & 31, wid = tid >> 5;
    int is64 = g_is64;

    // Stage W1c (cols 128..191) split hi/lo, K-major rows padded to 144B
    for (int i = tid; i < HDIM * 16; i += THREADS) {
        int o = i >> 4, r = i & 15;
        float4 v = *(const float4*)(W1 + o * HDIM + 128 + r * 4);
        uint2 lo, hi = pack_hi_lo(v, &lo);
        *(uint2*)(sm + OFF_WHI + o * ROWB + r * 8) = hi;
        *(uint2*)(sm + OFF_WLO + o * ROWB + r * 8) = lo;
    }
    for (int i = tid; i < HDIM; i += THREADS) W2s[i] = W2[i];
    __syncthreads();

    char* Ahi = sm + OFF_A + wid * AWARP;
    char* Alo = Ahi + 2304;
    uint32_t ahi_u = smb + OFF_A + wid * AWARP;
    uint32_t alo_u = ahi_u + 2304;
    int*   sSw = (int*)(sm + OFF_SS) + wid * 16;
    int*   sDw = (int*)(sm + OFF_SD) + wid * 16;
    float* ATw = (float*)(sm + OFF_AT) + wid * 16;

    int gw = blockIdx.x * NWARP + wid;
    for (int wt = gw; wt < nwt; wt += gridDim.x * NWARP) {
        int tbase = wt * 16;
        // ---- stage indices ----
        if (lane < 16) {
            int ge = tbase + lane;
            int s = 0, d = 0;
            if (ge < E) {
                s = (int)ldidx(ei, ge, is64);
                d = (int)ldidx(ei, E + ge, is64);
            }
            sSw[lane] = s; sDw[lane] = d;
        }
        __syncwarp();
        // ---- gather adj rows + bf16 split into private A buffers ----
        {
            int r = lane >> 1, h = lane & 1;
            int ge = tbase + r;
            int s = sSw[r], d = sDw[r];
            const float4* rowp =
                (const float4*)(adj + ((long long)s * NNODES + (d & (NNODES - 1))) * D);
            #pragma unroll
            for (int j = 0; j < 8; ++j) {
                float4 v = (ge < E) ? rowp[h * 8 + j]
                                    : make_float4(0.f, 0.f, 0.f, 0.f);
                uint2 lo, hi = pack_hi_lo(v, &lo);
                *(uint2*)(Ahi + r * ROWB + h * 64 + j * 8) = hi;
                *(uint2*)(Alo + r * ROWB + h * 64 + j * 8) = lo;
            }
        }
        __syncwarp();

        int r0 = lane >> 2, r1 = r0 + 8;
        int s0 = sSw[r0], d0 = sDw[r0], s1 = sSw[r1], d1 = sDw[r1];
        const float* pd0 = g_Pd + d0 * HDIM;
        const float* ps0 = g_Ps + s0 * HDIM;
        const float* pd1 = g_Pd + d1 * HDIM;
        const float* ps1 = g_Ps + s1 * HDIM;

        float z0 = 0.0f, z1 = 0.0f;
        #pragma unroll
        for (int nc = 0; nc < 3; ++nc) {
            float acc[8][4];
            int cb = nc * 64;
            #pragma unroll
            for (int f = 0; f < 8; ++f) {
                int c0 = cb + f * 8 + 2 * (lane & 3);
                float2 a0 = *(const float2*)(pd0 + c0);
                float2 b0 = *(const float2*)(ps0 + c0);
                float2 a1 = *(const float2*)(pd1 + c0);
                float2 b1 = *(const float2*)(ps1 + c0);
                acc[f][0] = a0.x + b0.x; acc[f][1] = a0.y + b0.y;
                acc[f][2] = a1.x + b1.x; acc[f][3] = a1.y + b1.y;
            }
            #pragma unroll
            for (int kk = 0; kk < 4; ++kk) {
                uint32_t aoff = (uint32_t)((lane & 15) * ROWB + kk * 32 + (lane >> 4) * 16);
                uint32_t ah[4], al[4];
                ldsm4(ah, ahi_u + aoff);
                ldsm4(al, alo_u + aoff);
                #pragma unroll
                for (int f = 0; f < 8; ++f) {
                    uint32_t boff = (uint32_t)((cb + f * 8 + (lane & 7)) * ROWB
                                               + kk * 32 + ((lane >> 3) & 1) * 16);
                    uint32_t bh[2], bl[2];
                    ldsm2(bh, smb + OFF_WHI + boff);
                    ldsm2(bl, smb + OFF_WLO + boff);
                    mma_bf16(acc[f], ah, bh);
                    mma_bf16(acc[f], ah, bl);
                    mma_bf16(acc[f], al, bh);
                }
            }
            #pragma unroll
            for (int f = 0; f < 8; ++f) {
                int c0 = cb + f * 8 + 2 * (lane & 3);
                float w0 = W2s[c0], w1 = W2s[c0 + 1];
                z0 = fmaf(gelu_x(acc[f][0]), w0, z0);
                z0 = fmaf(gelu_x(acc[f][1]), w1, z0);
                z1 = fmaf(gelu_x(acc[f][2]), w0, z1);
                z1 = fmaf(gelu_x(acc[f][3]), w1, z1);
            }
        }
        // quad reduce (lanes sharing the same rows)
        z0 += __shfl_xor_sync(0xffffffffu, z0, 1);
        z0 += __shfl_xor_sync(0xffffffffu, z0, 2);
        z1 += __shfl_xor_sync(0xffffffffu, z1, 1);
        z1 += __shfl_xor_sync(0xffffffffu, z1, 2);

        if ((lane & 3) == 0) {
            int df0 = (s0 > d0 ? s0 - d0 : d0 - s0);
            int df1 = (s1 > d1 ? s1 - d1 : d1 - s1);
            float at0 = (tbase + r0 < E && df0 > 1) ? expf(z0) : 0.0f;
            float at1 = (tbase + r1 < E && df1 > 1) ? expf(z1) : 0.0f;
            ATw[r0] = at0; ATw[r1] = at1;
            if (at0 != 0.0f) atomicAdd(&g_denom[d0], at0);
            if (at1 != 0.0f) atomicAdd(&g_denom[d1], at1);
        }
        __syncwarp();

        // weighted accumulate: 2 edges per pass (lane>>4 selects), 4 cols/lane
        #pragma unroll
        for (int ep = 0; ep < 8; ++ep) {
            int e = ep * 2 + (lane >> 4);
            float a = ATw[e];
            if (a != 0.0f) {
                int c4 = lane & 15;
                uint2 hi = *(uint2*)(Ahi + e * ROWB + c4 * 8);
                uint2 lo = *(uint2*)(Alo + e * ROWB + c4 * 8);
                float2 h0 = ubf2(hi.x), h1 = ubf2(hi.y);
                float2 l0 = ubf2(lo.x), l1 = ubf2(lo.y);
                float* op = out + sDw[e] * D + c4 * 4;
                red4(op, (h0.x + l0.x) * a, (h0.y + l0.y) * a,
                         (h1.x + l1.x) * a, (h1.y + l1.y) * a);
            }
        }
        __syncwarp();
    }
}

__global__ void finalize_kernel(float* __restrict__ out) {
    int i = blockIdx.x * blockDim.x + threadIdx.x;
    if (i < NTOT * D) {
        float dn = g_denom[i >> 6];
        out[i] = out[i] / (dn == 0.0f ? 1.0f : dn);
    }
}

extern "C" void kernel_launch(void* const* d_in, const int* in_sizes, int n_in,
                              void* d_out, int out_size) {
    const float* nf  = (const float*)d_in[0];
    const float* adj = (const float*)d_in[1];
    const float* W1  = (const float*)d_in[2];
    const float* W2  = (const float*)d_in[3];
    const void*  ei  = d_in[4];
    int E = in_sizes[4] / 2;
    if (E > EMAX) E = EMAX;

    const int pre_smem = (64 * HDIM + 64 * 64) * sizeof(float);
    cudaFuncSetAttribute(precompute_kernel, cudaFuncAttributeMaxDynamicSharedMemorySize, pre_smem);
    cudaFuncSetAttribute(score_kernel, cudaFuncAttributeMaxDynamicSharedMemorySize, SMEM_TOTAL);

    detect_kernel<<<1, 1024>>>(ei);
    zero_kernel<<<(NTOT * D + 255) / 256, 256>>>((float*)d_out);
    precompute_kernel<<<(NTOT / 64) * 2, 256, pre_smem>>>(nf, W1);

    int nwt = (E + 15) / 16;
    int grid = 148;
    score_kernel<<<grid, THREADS, SMEM_TOTAL>>>(adj, W1, W2, ei, (float*)d_out, E, nwt);

    finalize_kernel<<<(NTOT * D + 255) / 256, 256>>>((float*)d_out);
}